// round 13
// baseline (speedup 1.0000x reference)
#include <cuda_runtime.h>

typedef unsigned long long ULL;

__device__ __forceinline__ ULL pack2(float a, float b){
    ULL r; asm("mov.b64 %0, {%1, %2};" : "=l"(r) : "f"(a), "f"(b)); return r;
}
__device__ __forceinline__ void unpack2(ULL v, float& a, float& b){
    asm("mov.b64 {%0, %1}, %2;" : "=f"(a), "=f"(b) : "l"(v));
}
// Packed dual-fp32 ops (Blackwell f32x2) — ptxas never auto-fuses; must be PTX.
__device__ __forceinline__ ULL ffma2(ULL a, ULL b, ULL c){
    ULL d; asm("fma.rn.f32x2 %0, %1, %2, %3;" : "=l"(d) : "l"(a), "l"(b), "l"(c)); return d;
}
__device__ __forceinline__ ULL fadd2(ULL a, ULL b){
    ULL d; asm("add.rn.f32x2 %0, %1, %2;" : "=l"(d) : "l"(a), "l"(b)); return d;
}
__device__ __forceinline__ ULL fmul2(ULL a, ULL b){
    ULL d; asm("mul.rn.f32x2 %0, %1, %2;" : "=l"(d) : "l"(a), "l"(b)); return d;
}
__device__ __forceinline__ float celu1(float v){
    return v > 0.f ? v : (__expf(v) - 1.f);
}

#define EMAX 786432

// ---- device scratch (static __device__ arrays: the allowed scratch path) ----
__device__ int   g_start[32769];
__device__ ULL   g_H[EMAX * 16 + 16];    // per-edge h, PRE-DUPLICATED (h,h): 128 B/edge (+pad)
__device__ float g_X[EMAX * 16 + 64];    // per-edge raw x row: 64 B/edge (+pad)
__device__ float g_P[32768 * 1024];      // 128 MB intermediate P = x^T M per point

// Boundary-detection segment starts: g_start[n] = first edge i with out_index[i] >= n.
__global__ void starts_kernel(const int* __restrict__ out_index, int E, int Npts){
    int i = blockIdx.x * blockDim.x + threadIdx.x;
    if (i >= E) return;
    const int cur  = out_index[i];
    const int prev = (i == 0) ? -1 : out_index[i - 1];
    for (int n = prev + 1; n <= cur; ++n) g_start[n] = i;
    if (i == E - 1)
        for (int n = cur + 1; n <= Npts; ++n) g_start[n] = E;
}

// ---------------- Phase 0: dense per-edge gather + layer-1 MLP ----------------
// 4 threads per edge. Each thread: computes 4 of the 16 h = celu(d @ W1) values
// (stored dup'd as (h,h) ULLs) and copies 4 of the 16 x channels. All writes
// perfectly coalesced; the random pos_in/x_in gathers are hidden by 3.1M threads.
__global__ __launch_bounds__(256)
void gather_kernel(const float* __restrict__ x_in, const float* __restrict__ pos_in,
                   const float* __restrict__ pos_out, const int* __restrict__ in_index,
                   const int* __restrict__ out_index, const float* __restrict__ W1, int E)
{
    const int gid = blockIdx.x * blockDim.x + threadIdx.x;
    const int e   = gid >> 2;
    const int sub = gid & 3;
    if (e >= E) return;

    const int idx = in_index[e];
    const int o   = out_index[e];
    const float d0 = pos_in[idx * 3]     - pos_out[o * 3];
    const float d1 = pos_in[idx * 3 + 1] - pos_out[o * 3 + 1];
    const float d2 = pos_in[idx * 3 + 2] - pos_out[o * 3 + 2];

    ULL h[4];
    #pragma unroll
    for (int j0 = 0; j0 < 4; ++j0) {
        const int j = sub * 4 + j0;
        const float hj = celu1(fmaf(d2, W1[32 + j], fmaf(d1, W1[16 + j], d0 * W1[j])));
        h[j0] = pack2(hj, hj);
    }
    ulonglong2* Hd = (ulonglong2*)(g_H + (ULL)e * 16 + sub * 4);
    Hd[0] = make_ulonglong2(h[0], h[1]);
    Hd[1] = make_ulonglong2(h[2], h[3]);

    const float4 xv = *(const float4*)(x_in + (ULL)idx * 16 + sub * 4);
    *(float4*)(g_X + (ULL)e * 16 + sub * 4) = xv;
}

// ---------------- Phase 1: per-point streaming aggregation -> P ----------------
// One warp per point, one edge per iteration. All operands STREAM from g_H/g_X
// (contiguous per warp, prefetched one edge ahead). Lane l owns M cols {l, l+32}.
// acc0[q] = (P[2q][l], P[2q+1][l]); x channel-pairs come bit-identical from the
// float stream (no packing); h arrives pre-duplicated (no dup-MOVs).
__global__ __launch_bounds__(128)
void edge_kernel(const float* __restrict__ W2, int Npts)
{
    const int w = threadIdx.x >> 5;
    const int l = threadIdx.x & 31;
    const int n = blockIdx.x * 4 + w;
    if (n >= Npts) return;

    const int s    = g_start[n];
    const int cnt  = g_start[n + 1] - s;
    const float inv = cnt > 0 ? 1.f / (float)cnt : 0.f;
    const int lim  = cnt < 64 ? cnt : 64;   // reference drops edges past K=64 slots

    // w2col[j] = (W2[j][l], W2[j][l+32])
    ULL w2col[16];
    #pragma unroll
    for (int j = 0; j < 16; ++j)
        w2col[j] = pack2(W2[j * 64 + l], W2[j * 64 + l + 32]);

    ULL acc0[8], acc1[8];
    #pragma unroll
    for (int q = 0; q < 8; ++q) { acc0[q] = 0ull; acc1[q] = 0ull; }

    const ulonglong2* Hs = (const ulonglong2*)(g_H + (ULL)s * 16);  // 8 u2 per edge
    const ulonglong2* Xs = (const ulonglong2*)(g_X + (ULL)s * 16);  // 4 u2 per edge

    // prefetch edge 0 (padded arrays make the s==E read safe)
    ulonglong2 hc[8], xc[4];
    #pragma unroll
    for (int i = 0; i < 8; ++i) hc[i] = Hs[i];
    #pragma unroll
    for (int i = 0; i < 4; ++i) xc[i] = Xs[i];

    for (int t = 0; t < lim; ++t) {
        // prefetch edge t+1 (reads past the segment stay inside padded arrays)
        ulonglong2 hn[8], xn[4];
        const ulonglong2* Hn = Hs + (t + 1) * 8;
        const ulonglong2* Xn = Xs + (t + 1) * 4;
        #pragma unroll
        for (int i = 0; i < 8; ++i) hn[i] = Hn[i];
        #pragma unroll
        for (int i = 0; i < 4; ++i) xn[i] = Xn[i];

        // M cols {l, l+32}: two 8-deep ffma2 chains over pre-dup'd h
        ULL m0 = fmul2(hc[0].x, w2col[0]);
        ULL m1 = fmul2(hc[0].y, w2col[1]);
        m0 = ffma2(hc[1].x, w2col[2],  m0);  m1 = ffma2(hc[1].y, w2col[3],  m1);
        m0 = ffma2(hc[2].x, w2col[4],  m0);  m1 = ffma2(hc[2].y, w2col[5],  m1);
        m0 = ffma2(hc[3].x, w2col[6],  m0);  m1 = ffma2(hc[3].y, w2col[7],  m1);
        m0 = ffma2(hc[4].x, w2col[8],  m0);  m1 = ffma2(hc[4].y, w2col[9],  m1);
        m0 = ffma2(hc[5].x, w2col[10], m0);  m1 = ffma2(hc[5].y, w2col[11], m1);
        m0 = ffma2(hc[6].x, w2col[12], m0);  m1 = ffma2(hc[6].y, w2col[13], m1);
        m0 = ffma2(hc[7].x, w2col[14], m0);  m1 = ffma2(hc[7].y, w2col[15], m1);
        float ml, mr;
        { ULL m = fadd2(m0, m1); float a, b; unpack2(m, a, b); ml = celu1(a); mr = celu1(b); }
        const ULL mld = pack2(ml, ml);       // (M_l, M_l)
        const ULL mrd = pack2(mr, mr);       // (M_{l+32}, M_{l+32})

        // outer product: x channel-pairs straight from the stream
        acc0[0] = ffma2(xc[0].x, mld, acc0[0]);  acc1[0] = ffma2(xc[0].x, mrd, acc1[0]);
        acc0[1] = ffma2(xc[0].y, mld, acc0[1]);  acc1[1] = ffma2(xc[0].y, mrd, acc1[1]);
        acc0[2] = ffma2(xc[1].x, mld, acc0[2]);  acc1[2] = ffma2(xc[1].x, mrd, acc1[2]);
        acc0[3] = ffma2(xc[1].y, mld, acc0[3]);  acc1[3] = ffma2(xc[1].y, mrd, acc1[3]);
        acc0[4] = ffma2(xc[2].x, mld, acc0[4]);  acc1[4] = ffma2(xc[2].x, mrd, acc1[4]);
        acc0[5] = ffma2(xc[2].y, mld, acc0[5]);  acc1[5] = ffma2(xc[2].y, mrd, acc1[5]);
        acc0[6] = ffma2(xc[3].x, mld, acc0[6]);  acc1[6] = ffma2(xc[3].x, mrd, acc1[6]);
        acc0[7] = ffma2(xc[3].y, mld, acc0[7]);  acc1[7] = ffma2(xc[3].y, mrd, acc1[7]);

        #pragma unroll
        for (int i = 0; i < 8; ++i) hc[i] = hn[i];
        #pragma unroll
        for (int i = 0; i < 4; ++i) xc[i] = xn[i];
    }

    // store P[n][c*64+m], applying the folded 1/cnt (coalesced 128B rows)
    float* Pn = g_P + (ULL)n * 1024;
    const ULL invd = pack2(inv, inv);
    #pragma unroll
    for (int q = 0; q < 8; ++q) {
        float a, b;
        unpack2(fmul2(acc0[q], invd), a, b);
        Pn[(2 * q)     * 64 + l] = a;
        Pn[(2 * q + 1) * 64 + l] = b;
        unpack2(fmul2(acc1[q], invd), a, b);
        Pn[(2 * q)     * 64 + l + 32] = a;
        Pn[(2 * q + 1) * 64 + l + 32] = b;
    }
}

// ---------------- Phase 2: out = P @ W3 + b3  (smem-tiled GEMM) ----------------
__global__ __launch_bounds__(256)
void gemm_kernel(const float* __restrict__ W3, const float* __restrict__ b3,
                 float* __restrict__ out, int Npts)
{
    __shared__ ULL As[32][128];   // 32 KB, dup'd P tile (transposed)
    __shared__ ULL Bs[32][32];    // 8 KB,  W3 tile (col-pairs)

    const int tid = threadIdx.x;
    const int n0  = blockIdx.x * 128;

    const int rg = tid >> 4;
    const int g  = tid & 15;
    const int r0 = rg * 8;

    ULL acc0[8], acc1[8];
    #pragma unroll
    for (int r = 0; r < 8; ++r) { acc0[r] = 0ull; acc1[r] = 0ull; }

    const int ra   = tid >> 1;
    const int koff = (tid & 1) * 16;
    const float* Pa = g_P + (ULL)(n0 + ra) * 1024 + koff;
    const int kb = tid >> 3;
    const int cb = (tid & 7) * 8;

    for (int kc = 0; kc < 1024; kc += 32) {
        #pragma unroll
        for (int q = 0; q < 4; ++q) {
            const float4 f = *(const float4*)(Pa + kc + q * 4);
            As[koff + q * 4    ][ra] = pack2(f.x, f.x);
            As[koff + q * 4 + 1][ra] = pack2(f.y, f.y);
            As[koff + q * 4 + 2][ra] = pack2(f.z, f.z);
            As[koff + q * 4 + 3][ra] = pack2(f.w, f.w);
        }
        {
            const float4 f0 = *(const float4*)(W3 + (kc + kb) * 64 + cb);
            const float4 f1 = *(const float4*)(W3 + (kc + kb) * 64 + cb + 4);
            *(float4*)&Bs[kb][cb >> 1]       = f0;
            *(float4*)&Bs[kb][(cb >> 1) + 2] = f1;
        }
        __syncthreads();

        #pragma unroll 16
        for (int k = 0; k < 32; ++k) {
            const ulonglong2 a01 = *(const ulonglong2*)&As[k][r0];
            const ulonglong2 a23 = *(const ulonglong2*)&As[k][r0 + 2];
            const ulonglong2 a45 = *(const ulonglong2*)&As[k][r0 + 4];
            const ulonglong2 a67 = *(const ulonglong2*)&As[k][r0 + 6];
            const ulonglong2 bb  = *(const ulonglong2*)&Bs[k][2 * g];
            acc0[0] = ffma2(a01.x, bb.x, acc0[0]);  acc1[0] = ffma2(a01.x, bb.y, acc1[0]);
            acc0[1] = ffma2(a01.y, bb.x, acc0[1]);  acc1[1] = ffma2(a01.y, bb.y, acc1[1]);
            acc0[2] = ffma2(a23.x, bb.x, acc0[2]);  acc1[2] = ffma2(a23.x, bb.y, acc1[2]);
            acc0[3] = ffma2(a23.y, bb.x, acc0[3]);  acc1[3] = ffma2(a23.y, bb.y, acc1[3]);
            acc0[4] = ffma2(a45.x, bb.x, acc0[4]);  acc1[4] = ffma2(a45.x, bb.y, acc1[4]);
            acc0[5] = ffma2(a45.y, bb.x, acc0[5]);  acc1[5] = ffma2(a45.y, bb.y, acc1[5]);
            acc0[6] = ffma2(a67.x, bb.x, acc0[6]);  acc1[6] = ffma2(a67.x, bb.y, acc1[6]);
            acc0[7] = ffma2(a67.y, bb.x, acc0[7]);  acc1[7] = ffma2(a67.y, bb.y, acc1[7]);
        }
        __syncthreads();
    }

    const ULL b3p0 = pack2(b3[4 * g],     b3[4 * g + 1]);
    const ULL b3p1 = pack2(b3[4 * g + 2], b3[4 * g + 3]);
    #pragma unroll
    for (int r = 0; r < 8; ++r) {
        const int n = n0 + r0 + r;
        if (n < Npts) {
            const ULL s0 = fadd2(acc0[r], b3p0);
            const ULL s1 = fadd2(acc1[r], b3p1);
            float4 o;
            unpack2(s0, o.x, o.y);
            unpack2(s1, o.z, o.w);
            *(float4*)(out + n * 64 + 4 * g) = o;
        }
    }
}

extern "C" void kernel_launch(void* const* d_in, const int* in_sizes, int n_in,
                              void* d_out, int out_size)
{
    const float* x_in    = (const float*)d_in[0];
    const float* pos_in  = (const float*)d_in[1];
    const float* pos_out = (const float*)d_in[2];
    const int*  in_index = (const int*)  d_in[3];
    const int* out_index = (const int*)  d_in[4];
    const float* W1 = (const float*)d_in[5];
    const float* W2 = (const float*)d_in[6];
    const float* W3 = (const float*)d_in[7];
    const float* b3 = (const float*)d_in[8];
    float* out = (float*)d_out;

    const int E    = in_sizes[3];
    const int Npts = in_sizes[0] / 16;   // x_in is [N, 16]

    starts_kernel<<<(E + 255) / 256, 256>>>(out_index, E, Npts);
    gather_kernel<<<(E * 4 + 255) / 256, 256>>>(x_in, pos_in, pos_out, in_index,
                                                out_index, W1, E);
    edge_kernel<<<(Npts + 3) / 4, 128>>>(W2, Npts);
    gemm_kernel<<<(Npts + 127) / 128, 256>>>(W3, b3, out, Npts);
}